// round 1
// baseline (speedup 1.0000x reference)
#include <cuda_runtime.h>

// Problem constants (fixed shapes from reference)
#define B_DIM  8
#define C_DIM  256
#define HW     4096          // 64*64
#define O_DIM  256
#define R_DIM  8
#define K_DIM  2048          // C_DIM * R_DIM, k = c*8 + r

// Tile config
#define TM 128
#define TN 128
#define TK 16
#define NTHREADS 256

// out[b,o,p] = sum_{c,r} mat0[b,c,p] * mat1[o,c,r] * Alpha[r] * mask[r,p]
// GEMM view:  C[o, (b,p)] = A[o, k] * X[k, (b,p)]
//   A  = mat1 as [O, K] row-major (k = c*8+r is mat1's native layout)
//   X[k,n] = mat0[b,c,p] * maskA[r,p],  maskA[r,p] = mask[r,p]*(use_alpha?Alpha[r]:1)
__global__ __launch_bounds__(NTHREADS, 2)
void deform_mm_f32_kernel(const float* __restrict__ mat0,
                          const float* __restrict__ mat1,
                          const float* __restrict__ mask,
                          const float* __restrict__ Alpha,
                          const int*   __restrict__ use_alpha,
                          float*       __restrict__ out)
{
    __shared__ float As[TK][TM];           // A^T tile: As[kk][mm]
    __shared__ float Bs[TK][TN];           // X tile:   Bs[kk][nn]
    __shared__ float maskA[R_DIM][TN];     // per-tile alpha-scaled mask rows

    const int tid   = threadIdx.x;
    const int ntile = blockIdx.x;          // 0..255  (32 pixel-tiles per batch * 8 batches)
    const int mtile = blockIdx.y;          // 0..1
    const int b     = ntile >> 5;          // 4096/128 = 32 tiles per batch
    const int p0    = (ntile & 31) * TN;
    const int m0    = mtile * TM;

    // ---- load alpha-scaled mask rows for this pixel tile (once) ----
    {
        // Robust to use_alpha being int32 or float32: nonzero bits => true.
        const bool ua = (use_alpha[0] != 0);
        for (int i = tid; i < R_DIM * TN; i += NTHREADS) {
            const int r = i >> 7;          // TN = 128
            const int j = i & (TN - 1);
            const float a = ua ? Alpha[r] : 1.0f;
            maskA[r][j] = mask[r * HW + p0 + j] * a;
        }
    }
    __syncthreads();

    // micro-tile mapping: 16x16 thread grid, 8x8 per thread
    const int tx = tid & 15;               // column group
    const int ty = tid >> 4;               // row group

    float acc[8][8];
    #pragma unroll
    for (int i = 0; i < 8; i++)
        #pragma unroll
        for (int j = 0; j < 8; j++)
            acc[i][j] = 0.0f;

    const float* mat0_b = mat0 + (size_t)b * C_DIM * HW + p0;

    // A-load mapping: thread handles row mm = tid>>1, 8 consecutive k at (tid&1)*8
    const int a_mm = tid >> 1;
    const int a_kb = (tid & 1) * 8;
    const float* a_row = mat1 + (size_t)(m0 + a_mm) * K_DIM + a_kb;

    for (int k0 = 0; k0 < K_DIM; k0 += TK) {
        // ---- load A tile (transposed into As[kk][mm]) ----
        {
            const float4 v0 = *reinterpret_cast<const float4*>(a_row + k0);
            const float4 v1 = *reinterpret_cast<const float4*>(a_row + k0 + 4);
            As[a_kb + 0][a_mm] = v0.x;  As[a_kb + 1][a_mm] = v0.y;
            As[a_kb + 2][a_mm] = v0.z;  As[a_kb + 3][a_mm] = v0.w;
            As[a_kb + 4][a_mm] = v1.x;  As[a_kb + 5][a_mm] = v1.y;
            As[a_kb + 6][a_mm] = v1.z;  As[a_kb + 7][a_mm] = v1.w;
        }

        // ---- build B (X) tile on the fly ----
        // k = c*8 + r  =>  this K-step covers c in {k0>>3, (k0>>3)+1}
        {
            const int c0 = k0 >> 3;
            #pragma unroll
            for (int it = 0; it < (TK * TN) / NTHREADS; it++) {
                const int i  = tid + it * NTHREADS;
                const int kk = i >> 7;                 // 0..15
                const int nn = i & (TN - 1);
                const int c  = c0 + (kk >> 3);
                const int r  = kk & 7;
                Bs[kk][nn] = mat0_b[c * HW + nn] * maskA[r][nn];
            }
        }
        __syncthreads();

        // ---- FFMA micro-kernel ----
        #pragma unroll
        for (int kk = 0; kk < TK; kk++) {
            float a[8], bb[8];
            {
                const float4 a0 = *reinterpret_cast<const float4*>(&As[kk][ty * 8]);
                const float4 a1 = *reinterpret_cast<const float4*>(&As[kk][ty * 8 + 4]);
                a[0]=a0.x; a[1]=a0.y; a[2]=a0.z; a[3]=a0.w;
                a[4]=a1.x; a[5]=a1.y; a[6]=a1.z; a[7]=a1.w;
                const float4 b0 = *reinterpret_cast<const float4*>(&Bs[kk][tx * 8]);
                const float4 b1 = *reinterpret_cast<const float4*>(&Bs[kk][tx * 8 + 4]);
                bb[0]=b0.x; bb[1]=b0.y; bb[2]=b0.z; bb[3]=b0.w;
                bb[4]=b1.x; bb[5]=b1.y; bb[6]=b1.z; bb[7]=b1.w;
            }
            #pragma unroll
            for (int i = 0; i < 8; i++)
                #pragma unroll
                for (int j = 0; j < 8; j++)
                    acc[i][j] = fmaf(a[i], bb[j], acc[i][j]);
        }
        __syncthreads();
    }

    // ---- epilogue: out[b, o, p] ----
    float* out_base = out + (size_t)b * O_DIM * HW + p0;
    #pragma unroll
    for (int i = 0; i < 8; i++) {
        const int o = m0 + ty * 8 + i;
        float* orow = out_base + (size_t)o * HW + tx * 8;
        float4 w0 = make_float4(acc[i][0], acc[i][1], acc[i][2], acc[i][3]);
        float4 w1 = make_float4(acc[i][4], acc[i][5], acc[i][6], acc[i][7]);
        *reinterpret_cast<float4*>(orow)     = w0;
        *reinterpret_cast<float4*>(orow + 4) = w1;
    }
}

extern "C" void kernel_launch(void* const* d_in, const int* in_sizes, int n_in,
                              void* d_out, int out_size)
{
    const float* mat0      = (const float*)d_in[0];   // [8,256,64,64]
    const float* mat1      = (const float*)d_in[1];   // [256,256,8]
    const float* mask      = (const float*)d_in[2];   // [8,64,64]
    const float* Alpha     = (const float*)d_in[3];   // [8]
    const int*   use_alpha = (const int*)  d_in[4];   // scalar
    // d_in[5] = beta (unused by reference math)
    float* out = (float*)d_out;                       // [8,256,64,64]

    dim3 grid(B_DIM * (HW / TN), O_DIM / TM);         // (256, 2)
    deform_mm_f32_kernel<<<grid, NTHREADS>>>(mat0, mat1, mask, Alpha, use_alpha, out);
}

// round 5
// speedup vs baseline: 3.1781x; 3.1781x over previous
#include <cuda_runtime.h>
#include <cstdint>

// Shapes (fixed)
#define HW     4096
#define O_DIM  256
#define K_DIM  2048          // k = c*8 + r

// Tiling
#define TM 128
#define TN 256
#define TK 64                // 8 channels per chunk
#define NCHUNK 32
#define NTHREADS 256

// smem per buffer: A 64x128 f32 (32KB) + B 64x256 f32 (64KB)
#define A_WORDS   (64 * 128)
#define B_WORDS   (64 * 256)
#define BUF_WORDS (A_WORDS + B_WORDS)          // 24576 words = 96KB
#define SMEM_BYTES (2 * BUF_WORDS * 4)         // 192KB

static __device__ __forceinline__ uint32_t f2tf32(float x) {
    uint32_t r;
    asm("cvt.rna.tf32.f32 %0, %1;" : "=r"(r) : "f"(x));
    return r;
}

static __device__ __forceinline__ void mma_tf32(float d[4], const uint32_t a[4],
                                                uint32_t b0, uint32_t b1) {
    asm volatile("mma.sync.aligned.m16n8k8.row.col.f32.tf32.tf32.f32 "
                 "{%0,%1,%2,%3}, {%4,%5,%6,%7}, {%8,%9}, {%0,%1,%2,%3};"
                 : "+f"(d[0]), "+f"(d[1]), "+f"(d[2]), "+f"(d[3])
                 : "r"(a[0]), "r"(a[1]), "r"(a[2]), "r"(a[3]), "r"(b0), "r"(b1));
}

extern __shared__ uint32_t smem[];

// Build one K-chunk: A = mat1 tile (transposed to k-major, XOR swizzle),
// B = X[k,n] = mat0*maskA (k-major, XOR swizzle). Flat function, no lambda.
static __device__ __forceinline__
void build_chunk(uint32_t* __restrict__ As, const float* __restrict__ a_src_k,
                 int a_m, int a_h, int cl2, int n4,
                 const float (*mr)[4], float4 x0, float4 x1)
{
    uint32_t* Bs = As + A_WORDS;

    // ---- A copy: 32 floats/thread ----
    float4 v[8];
    #pragma unroll
    for (int q = 0; q < 8; q++)
        v[q] = *(const float4*)(a_src_k + q * 4);
    #pragma unroll
    for (int q = 0; q < 8; q++) {
        const int krow = a_h * 32 + q * 4;
        As[(krow + 0) * 128 + (a_m ^ 0 )] = f2tf32(v[q].x);
        As[(krow + 1) * 128 + (a_m ^ 8 )] = f2tf32(v[q].y);
        As[(krow + 2) * 128 + (a_m ^ 16)] = f2tf32(v[q].z);
        As[(krow + 3) * 128 + (a_m ^ 24)] = f2tf32(v[q].w);
    }

    // ---- B build: 2 channels x 8 regions x 4 pixels ----
    #pragma unroll
    for (int ci = 0; ci < 2; ci++) {
        const float4 x = ci ? x1 : x0;
        const int ch = cl2 * 2 + ci;
        #pragma unroll
        for (int r = 0; r < 8; r++) {
            uint4 y;
            y.x = f2tf32(x.x * mr[r][0]);
            y.y = f2tf32(x.y * mr[r][1]);
            y.z = f2tf32(x.z * mr[r][2]);
            y.w = f2tf32(x.w * mr[r][3]);
            const uint32_t col = ((uint32_t)(n4 * 4)) ^ (8u * (r & 3));
            *(uint4*)(Bs + (ch * 8 + r) * 256 + col) = y;
        }
    }
}

__global__ __launch_bounds__(NTHREADS, 1)
void deform_mma_kernel(const float* __restrict__ mat0,
                       const float* __restrict__ mat1,
                       const float* __restrict__ mask,
                       const float* __restrict__ Alpha,
                       const int*   __restrict__ use_alpha,
                       float*       __restrict__ out)
{
    const int tid  = threadIdx.x;
    const int wid  = tid >> 5;
    const int lane = tid & 31;

    const int nt = blockIdx.x;             // 0..127
    const int b  = nt >> 4;
    const int p0 = (nt & 15) * TN;
    const int m0 = blockIdx.y * TM;

    const int wm = (wid >> 2) * 64;        // warp m-offset (0/64)
    const int wn = (wid & 3) * 64;         // warp n-offset (0..192)

    const int c_id = lane & 3;
    const int g_id = lane >> 2;
    const uint32_t xk = 8u * c_id;

    // per-thread alpha-scaled mask (registers)
    const int n4 = tid & 63;
    float mr[8][4];
    {
        const bool ua = (use_alpha[0] != 0);
        #pragma unroll
        for (int r = 0; r < 8; r++) {
            const float a = ua ? Alpha[r] : 1.0f;
            const float4 mv = *(const float4*)(mask + r * HW + p0 + n4 * 4);
            mr[r][0] = mv.x * a; mr[r][1] = mv.y * a;
            mr[r][2] = mv.z * a; mr[r][3] = mv.w * a;
        }
    }

    const int cl2 = tid >> 6;
    const int a_m = tid >> 1;
    const int a_h = tid & 1;
    const float* a_src  = mat1 + (size_t)(m0 + a_m) * K_DIM + a_h * 32;
    const float* b_src0 = mat0 + ((size_t)b * 256) * HW + p0 + n4 * 4;

    float acc[4][8][4];
    #pragma unroll
    for (int mf = 0; mf < 4; mf++)
        #pragma unroll
        for (int nf = 0; nf < 8; nf++)
            #pragma unroll
            for (int x = 0; x < 4; x++) acc[mf][nf][x] = 0.0f;

    // prologue: build chunk 0
    {
        float4 x0 = *(const float4*)(b_src0 + (size_t)(cl2 * 2 + 0) * HW);
        float4 x1 = *(const float4*)(b_src0 + (size_t)(cl2 * 2 + 1) * HW);
        build_chunk(smem, a_src, a_m, a_h, cl2, n4, mr, x0, x1);
    }

    for (int kc = 0; kc < NCHUNK; kc++) {
        // prefetch next chunk's gmem B inputs
        float4 x0, x1;
        if (kc + 1 < NCHUNK) {
            x0 = *(const float4*)(b_src0 + (size_t)((kc + 1) * 8 + cl2 * 2 + 0) * HW);
            x1 = *(const float4*)(b_src0 + (size_t)((kc + 1) * 8 + cl2 * 2 + 1) * HW);
        }

        __syncthreads();

        const uint32_t* As = smem + (kc & 1) * BUF_WORDS;
        const uint32_t* Bs = As + A_WORDS;

        #pragma unroll
        for (int s = 0; s < 8; s++) {
            const int k0 = s * 8 + c_id;
            uint32_t a[4][4];
            #pragma unroll
            for (int mf = 0; mf < 4; mf++) {
                const uint32_t mlo = (uint32_t)(wm + mf * 16 + g_id) ^ xk;
                const uint32_t mhi = (uint32_t)(wm + mf * 16 + g_id + 8) ^ xk;
                a[mf][0] = As[(k0    ) * 128 + mlo];
                a[mf][1] = As[(k0    ) * 128 + mhi];
                a[mf][2] = As[(k0 + 4) * 128 + mlo];
                a[mf][3] = As[(k0 + 4) * 128 + mhi];
            }
            #pragma unroll
            for (int nf = 0; nf < 8; nf++) {
                const uint32_t ncol = (uint32_t)(wn + 8 * (nf ^ c_id) + g_id);
                const uint32_t b0 = Bs[(k0    ) * 256 + ncol];
                const uint32_t b1 = Bs[(k0 + 4) * 256 + ncol];
                #pragma unroll
                for (int mf = 0; mf < 4; mf++)
                    mma_tf32(acc[mf][nf], a[mf], b0, b1);
            }
        }

        if (kc + 1 < NCHUNK)
            build_chunk(smem + ((kc + 1) & 1) * BUF_WORDS,
                        a_src + (size_t)(kc + 1) * TK,
                        a_m, a_h, cl2, n4, mr, x0, x1);
    }

    // epilogue: c0:(g,2c) c1:(g,2c+1) c2:(g+8,2c) c3:(g+8,2c+1)
    {
        const int col = p0 + wn + 2 * c_id;
        #pragma unroll
        for (int mf = 0; mf < 4; mf++) {
            const int row = m0 + wm + mf * 16 + g_id;
            float* d0 = out + ((size_t)b * O_DIM + row    ) * HW + col;
            float* d1 = out + ((size_t)b * O_DIM + row + 8) * HW + col;
            #pragma unroll
            for (int nf = 0; nf < 8; nf++) {
                *(float2*)(d0 + nf * 8) = make_float2(acc[mf][nf][0], acc[mf][nf][1]);
                *(float2*)(d1 + nf * 8) = make_float2(acc[mf][nf][2], acc[mf][nf][3]);
            }
        }
    }
}

extern "C" void kernel_launch(void* const* d_in, const int* in_sizes, int n_in,
                              void* d_out, int out_size)
{
    const float* mat0      = (const float*)d_in[0];   // [8,256,64,64]
    const float* mat1      = (const float*)d_in[1];   // [256,256,8]
    const float* mask      = (const float*)d_in[2];   // [8,64,64]
    const float* Alpha     = (const float*)d_in[3];   // [8]
    const int*   use_alpha = (const int*)  d_in[4];
    float* out = (float*)d_out;                       // [8,256,64,64] f32

    static bool attr_done = false;
    if (!attr_done) {
        cudaFuncSetAttribute(deform_mma_kernel,
                             cudaFuncAttributeMaxDynamicSharedMemorySize, SMEM_BYTES);
        attr_done = true;
    }

    dim3 grid(128, 2);   // 128 n-tiles x 2 m-tiles
    deform_mma_kernel<<<grid, NTHREADS, SMEM_BYTES>>>(mat0, mat1, mask, Alpha, use_alpha, out);
}